// round 3
// baseline (speedup 1.0000x reference)
#include <cuda_runtime.h>

// Problem constants
#define BB   16
#define CC   256
#define HH   64
#define WW   192
#define DD   25
#define HWs  (HH*WW)
#define CHW  (512*HH*WW)
#define X2OFF ((size_t)CC*HWs)

// corr tiling
#define CK    4
#define ROWSK 4
#define TPB1  192
#define NROWS (CK*ROWSK)
#define X2W   (WW+24)

__device__ float g_corr[(size_t)BB*DD*HH*WW];

__device__ __forceinline__ void cp_async16(float* dst, const float* src) {
    unsigned d = (unsigned)__cvta_generic_to_shared(dst);
    asm volatile("cp.async.cg.shared.global [%0], [%1], 16;\n" :: "r"(d), "l"(src));
}

// packed fp32 fma: d = a*b + d  (FFMA2, sm_10x only via PTX)
__device__ __forceinline__ void ffma2(float2& d, const float2& a, const float2& b) {
    asm("fma.rn.f32x2 %0, %1, %2, %0;"
        : "+l"(reinterpret_cast<unsigned long long&>(d))
        : "l"(reinterpret_cast<const unsigned long long&>(a)),
          "l"(reinterpret_cast<const unsigned long long&>(b)));
}

__global__ __launch_bounds__(TPB1, 2)
void corr_kernel(const float* __restrict__ in) {
    __shared__ float x2s[2][NROWS * X2W];

    const int t  = threadIdx.x;
    const int b  = blockIdx.y;
    const int h0 = blockIdx.x * ROWSK;
    const int rr = t / 48;
    const int j  = t - rr * 48;
    const int w0 = 4 * j;

    for (int idx = t; idx < 2 * NROWS * 24; idx += TPB1) {
        int bu  = idx / (NROWS * 24);
        int rem = idx - bu * NROWS * 24;
        int row = rem / 24;
        int col = rem - row * 24;
        x2s[bu][row * X2W + col] = 0.0f;
    }

    const float* base   = in + (size_t)b * CHW + (size_t)h0 * WW;
    const float* x2base = base + X2OFF;

#define ISSUE_CHUNK(buf, ch) do {                                              \
    const float* p2 = x2base + (size_t)(ch) * CK * HWs;                        \
    _Pragma("unroll")                                                          \
    for (int it = 0; it < 4; it++) {                                           \
        int q   = it * TPB1 + t;                                               \
        int row = q / 48;                                                      \
        int col = (q - row * 48) * 4;                                          \
        int cl  = row >> 2;                                                    \
        int r   = row & 3;                                                     \
        cp_async16(&x2s[buf][row * X2W + 24 + col],                            \
                   p2 + (size_t)cl * HWs + (size_t)r * WW + col);              \
    }                                                                          \
    asm volatile("cp.async.commit_group;\n");                                  \
} while (0)

    float2 accxy[DD], acczw[DD];
    #pragma unroll
    for (int i = 0; i < DD; i++) {
        accxy[i] = make_float2(0.f, 0.f);
        acczw[i] = make_float2(0.f, 0.f);
    }

    const float* x1p = in + (size_t)b * CHW + (size_t)(h0 + rr) * WW + w0;
    float4 xp0 = __ldg((const float4*)x1p);
    float4 xp1 = __ldg((const float4*)(x1p + HWs));
    const float* x1n = x1p + 2 * (size_t)HWs;

    ISSUE_CHUNK(0, 0);

    for (int ch = 0; ch < CC / CK; ch++) {
        asm volatile("cp.async.wait_group 0;\n");
        __syncthreads();
        if (ch + 1 < CC / CK) ISSUE_CHUNK((ch + 1) & 1, ch + 1);

        const float* xr = &x2s[ch & 1][0];
        #pragma unroll
        for (int cl = 0; cl < CK; cl++) {
            float4 a = xp0; xp0 = xp1;
            xp1 = __ldg((const float4*)x1n); x1n += HWs;
            float2 axy = make_float2(a.x, a.y);
            float2 azw = make_float2(a.z, a.w);

            float v[28];
            const float4* r2 = (const float4*)(xr + (cl * ROWSK + rr) * X2W + w0);
            #pragma unroll
            for (int m = 0; m < 7; m++) ((float4*)v)[m] = r2[m];

            #pragma unroll
            for (int i = 0; i < DD; i++) {
                float2 bxy = make_float2(v[24 - i], v[25 - i]);
                float2 bzw = make_float2(v[26 - i], v[27 - i]);
                ffma2(accxy[i], axy, bxy);
                ffma2(acczw[i], azw, bzw);
            }
        }
    }

    size_t obase = (size_t)b * DD * HWs + (size_t)(h0 + rr) * WW + w0;
    #pragma unroll
    for (int i = 0; i < DD; i++) {
        float4 o = make_float4(accxy[i].x, accxy[i].y, acczw[i].x, acczw[i].y);
        *((float4*)(g_corr + obase + (size_t)i * HWs)) = o;
    }
#undef ISSUE_CHUNK
}

// ---------------- kernel 2: separable 3x3 box sum, single-sync tiles ----------------
#define BTH   16            // output rows per block
#define BSTR  200           // smem row stride (data cols 4..195; halo cols 3,196)
#define TPB2  256

__global__ __launch_bounds__(TPB2)
void box_kernel(float* __restrict__ out) {
    __shared__ float sIn[(BTH + 2) * BSTR];   // rows h0-1 .. h0+BTH
    __shared__ float sVs[BTH * BSTR];         // vertical sums

    const int t     = threadIdx.x;
    const int plane = blockIdx.x;             // b*25 + d
    const int h0    = blockIdx.y * BTH;

    const float* cp = g_corr + (size_t)plane * HWs;
    float*       op = out    + (size_t)plane * HWs;

    // zero w-halo columns (3 and 196) of sIn
    for (int r = t; r < BTH + 2; r += TPB2) {
        sIn[r * BSTR + 3]   = 0.f;
        sIn[r * BSTR + 196] = 0.f;
    }
    // load (BTH+2) x 192 floats as float4, zero-fill out-of-range rows
    {
        const int nf4 = (BTH + 2) * 48;      // float4s
        for (int i = t; i < nf4; i += TPB2) {
            int r  = i / 48;
            int c4 = i - r * 48;
            int h  = h0 + r - 1;
            float4 val = make_float4(0.f, 0.f, 0.f, 0.f);
            if (h >= 0 && h < HH) val = __ldg((const float4*)(cp + h * WW + c4 * 4));
            *((float4*)&sIn[r * BSTR + 4 + c4 * 4]) = val;
        }
    }
    __syncthreads();

    // vertical 3-sum over cols 3..196 (194 cols) for BTH rows
    {
        const int ncell = BTH * 194;
        for (int i = t; i < ncell; i += TPB2) {
            int r = i / 194;
            int c = i - r * 194 + 3;
            sVs[r * BSTR + c] = sIn[r * BSTR + c] + sIn[(r + 1) * BSTR + c] + sIn[(r + 2) * BSTR + c];
        }
    }
    __syncthreads();

    // horizontal 3-sum + store
    {
        const int ncell = BTH * WW;
        for (int i = t; i < ncell; i += TPB2) {
            int r = i / WW;
            int w = i - r * WW;
            const float* p = &sVs[r * BSTR + w + 3];
            op[(h0 + r) * WW + w] = p[0] + p[1] + p[2];
        }
    }
}

extern "C" void kernel_launch(void* const* d_in, const int* in_sizes, int n_in,
                              void* d_out, int out_size) {
    const float* in = (const float*)d_in[0];
    float* out = (float*)d_out;

    dim3 g1(HH / ROWSK, BB);          // 256 blocks
    corr_kernel<<<g1, TPB1>>>(in);

    dim3 g2(BB * DD, HH / BTH);       // (400, 4) = 1600 blocks
    box_kernel<<<g2, TPB2>>>(out);
}

// round 4
// speedup vs baseline: 1.0426x; 1.0426x over previous
#include <cuda_runtime.h>

// Problem constants
#define BB   16
#define CC   256
#define HH   64
#define WW   192
#define DD   25
#define HWs  (HH*WW)
#define CHW  (512*HH*WW)
#define X2OFF ((size_t)CC*HWs)

// corr tiling
#define CK    4
#define ROWSK 4
#define TPB1  192
#define NROWS (CK*ROWSK)
#define X2W   (WW+24)
#define NCH   (CC/CK)        // 64 chunks
#define NBUF  3              // cp.async pipeline depth

__device__ float g_corr[(size_t)BB*DD*HH*WW];

__device__ __forceinline__ void cp_async16(float* dst, const float* src) {
    unsigned d = (unsigned)__cvta_generic_to_shared(dst);
    asm volatile("cp.async.cg.shared.global [%0], [%1], 16;\n" :: "r"(d), "l"(src));
}

__global__ __launch_bounds__(TPB1, 2)
void corr_kernel(const float* __restrict__ in) {
    __shared__ float x2s[NBUF][NROWS * X2W];   // 3 * 13.5 KB

    const int t  = threadIdx.x;
    const int b  = blockIdx.y;
    const int h0 = blockIdx.x * ROWSK;
    const int rr = t / 48;
    const int j  = t - rr * 48;
    const int w0 = 4 * j;

    // zero the 24-col left pads of all buffers (never overwritten)
    for (int idx = t; idx < NBUF * NROWS * 24; idx += TPB1) {
        int bu  = idx / (NROWS * 24);
        int rem = idx - bu * NROWS * 24;
        int row = rem / 24;
        int col = rem - row * 24;
        x2s[bu][row * X2W + col] = 0.0f;
    }

    const float* base   = in + (size_t)b * CHW + (size_t)h0 * WW;
    const float* x2base = base + X2OFF;

#define ISSUE_CHUNK(buf, ch) do {                                              \
    const float* p2 = x2base + (size_t)(ch) * CK * HWs;                        \
    _Pragma("unroll")                                                          \
    for (int it = 0; it < 4; it++) {                                           \
        int q   = it * TPB1 + t;                                               \
        int row = q / 48;                                                      \
        int col = (q - row * 48) * 4;                                          \
        int cl  = row >> 2;                                                    \
        int r   = row & 3;                                                     \
        cp_async16(&x2s[buf][row * X2W + 24 + col],                            \
                   p2 + (size_t)cl * HWs + (size_t)r * WW + col);              \
    }                                                                          \
    asm volatile("cp.async.commit_group;\n");                                  \
} while (0)

    float4 acc[DD];
    #pragma unroll
    for (int i = 0; i < DD; i++) acc[i] = make_float4(0.f, 0.f, 0.f, 0.f);

    // x1 is exclusive per thread: direct coalesced LDG with depth-2 prefetch ring
    const float* x1p = in + (size_t)b * CHW + (size_t)(h0 + rr) * WW + w0;
    float4 xp0 = __ldg((const float4*)x1p);
    float4 xp1 = __ldg((const float4*)(x1p + HWs));
    const float* x1n = x1p + 2 * (size_t)HWs;   // overruns into x2 region (unused), safe

    ISSUE_CHUNK(0, 0);
    ISSUE_CHUNK(1, 1);

    int buf = 0;
    for (int ch = 0; ch < NCH; ch++) {
        if (ch + 1 < NCH) asm volatile("cp.async.wait_group 1;\n");
        else              asm volatile("cp.async.wait_group 0;\n");
        __syncthreads();                 // chunk ch visible everywhere; buf reuse safe
        if (ch + 2 < NCH) {
            int nb = buf + 2; if (nb >= NBUF) nb -= NBUF;
            ISSUE_CHUNK(nb, ch + 2);
        }

        const float* xr = &x2s[buf][0];
        #pragma unroll
        for (int cl = 0; cl < CK; cl++) {
            float4 a = xp0; xp0 = xp1;
            xp1 = __ldg((const float4*)x1n); x1n += HWs;

            float v[28];
            const float4* r2 = (const float4*)(xr + (cl * ROWSK + rr) * X2W + w0);
            #pragma unroll
            for (int m = 0; m < 7; m++) ((float4*)v)[m] = r2[m];
            #pragma unroll
            for (int i = 0; i < DD; i++) {
                acc[i].x = fmaf(a.x, v[24 - i], acc[i].x);
                acc[i].y = fmaf(a.y, v[25 - i], acc[i].y);
                acc[i].z = fmaf(a.z, v[26 - i], acc[i].z);
                acc[i].w = fmaf(a.w, v[27 - i], acc[i].w);
            }
        }
        if (++buf >= NBUF) buf = 0;
    }

    size_t obase = (size_t)b * DD * HWs + (size_t)(h0 + rr) * WW + w0;
    #pragma unroll
    for (int i = 0; i < DD; i++)
        *((float4*)(g_corr + obase + (size_t)i * HWs)) = acc[i];
#undef ISSUE_CHUNK
}

// ---------------- kernel 2: whole-plane 3x3 box sum, single sync ----------------
// smem plane: 66 rows (h=-1..64) x stride 200; data cols 4..195, zero halo cols 3,196.
#define BSTR 200
#define TPB2 192

__global__ __launch_bounds__(TPB2)
void box_kernel(float* __restrict__ out) {
    __shared__ float s[66 * BSTR];    // 52.8 KB

    const int t     = threadIdx.x;    // = w column
    const int plane = blockIdx.x;     // b*25 + d

    const float* cp = g_corr + (size_t)plane * HWs;
    float*       op = out    + (size_t)plane * HWs;

    // zero halo rows 0 and 65 (cols 3..196) and halo cols 3,196 of rows 1..64
    for (int i = t; i < 2 * 194; i += TPB2) {
        int r = (i < 194) ? 0 : 65;
        int c = (i < 194 ? i : i - 194) + 3;
        s[r * BSTR + c] = 0.f;
    }
    for (int r = t; r < 64; r += TPB2) { /* t<64 only */ }
    if (t < 64) {
        s[(t + 1) * BSTR + 3]   = 0.f;
        s[(t + 1) * BSTR + 196] = 0.f;
    }

    // load 64x192 plane as float4 (16 per thread), rows 1..64, col offset 4
    #pragma unroll
    for (int k = 0; k < 16; k++) {
        int idx = t + k * TPB2;          // 0..3071
        int row = idx / 48;
        int c4  = idx - row * 48;
        float4 v = __ldg((const float4*)(cp + row * WW + c4 * 4));
        *((float4*)&s[(row + 1) * BSTR + 4 + c4 * 4]) = v;
    }
    __syncthreads();

    // per-column rolling vertical sum of horizontal 3-sums
    const float* col = &s[4 + t];     // col[ (h+1)*BSTR ] = corr(h, t)
    float hsA = 0.f;                                           // hs(-1) = 0
    float hsB = col[BSTR - 1] + col[BSTR] + col[BSTR + 1];     // hs(0)
    #pragma unroll 4
    for (int h = 0; h < HH; h++) {
        const float* p = &col[(h + 2) * BSTR];
        float hsC = p[-1] + p[0] + p[1];                       // hs(h+1)
        op[h * WW + t] = hsA + hsB + hsC;
        hsA = hsB; hsB = hsC;
    }
}

extern "C" void kernel_launch(void* const* d_in, const int* in_sizes, int n_in,
                              void* d_out, int out_size) {
    const float* in = (const float*)d_in[0];
    float* out = (float*)d_out;

    dim3 g1(HH / ROWSK, BB);          // 256 blocks
    corr_kernel<<<g1, TPB1>>>(in);

    box_kernel<<<BB * DD, TPB2>>>(out);  // 400 blocks, one plane each
}

// round 5
// speedup vs baseline: 1.0465x; 1.0038x over previous
#include <cuda_runtime.h>

// Problem constants
#define BB   16
#define CC   256
#define HH   64
#define WW   192
#define DD   25
#define HWs  (HH*WW)
#define CHW  (512*HH*WW)
#define X2OFF ((size_t)CC*HWs)

// corr tiling
#define CK    4
#define ROWSK 4
#define TPB1  192
#define NROWS (CK*ROWSK)
#define X2W   (WW+24)
#define NCH   (CC/CK)        // 64 chunks
#define NBUF  3              // cp.async pipeline depth

__device__ float g_corr[(size_t)BB*DD*HH*WW];

__device__ __forceinline__ void cp_async16(float* dst, const float* src) {
    unsigned d = (unsigned)__cvta_generic_to_shared(dst);
    asm volatile("cp.async.cg.shared.global [%0], [%1], 16;\n" :: "r"(d), "l"(src));
}

__global__ __launch_bounds__(TPB1, 2)
void corr_kernel(const float* __restrict__ in) {
    __shared__ float x2s[NBUF][NROWS * X2W];   // 3 * 13.5 KB

    const int t  = threadIdx.x;
    const int b  = blockIdx.y;
    const int h0 = blockIdx.x * ROWSK;
    const int rr = t / 48;
    const int j  = t - rr * 48;
    const int w0 = 4 * j;

    // zero the 24-col left pads of all buffers (never overwritten)
    for (int idx = t; idx < NBUF * NROWS * 24; idx += TPB1) {
        int bu  = idx / (NROWS * 24);
        int rem = idx - bu * NROWS * 24;
        int row = rem / 24;
        int col = rem - row * 24;
        x2s[bu][row * X2W + col] = 0.0f;
    }

    const float* base   = in + (size_t)b * CHW + (size_t)h0 * WW;
    const float* x2base = base + X2OFF;

#define ISSUE_CHUNK(buf, ch) do {                                              \
    const float* p2 = x2base + (size_t)(ch) * CK * HWs;                        \
    _Pragma("unroll")                                                          \
    for (int it = 0; it < 4; it++) {                                           \
        int q   = it * TPB1 + t;                                               \
        int row = q / 48;                                                      \
        int col = (q - row * 48) * 4;                                          \
        int cl  = row >> 2;                                                    \
        int r   = row & 3;                                                     \
        cp_async16(&x2s[buf][row * X2W + 24 + col],                            \
                   p2 + (size_t)cl * HWs + (size_t)r * WW + col);              \
    }                                                                          \
    asm volatile("cp.async.commit_group;\n");                                  \
} while (0)

    float4 acc[DD];
    #pragma unroll
    for (int i = 0; i < DD; i++) acc[i] = make_float4(0.f, 0.f, 0.f, 0.f);

    // x1 is exclusive per thread: direct coalesced LDG with depth-2 prefetch ring
    const float* x1p = in + (size_t)b * CHW + (size_t)(h0 + rr) * WW + w0;
    float4 xp0 = __ldg((const float4*)x1p);
    float4 xp1 = __ldg((const float4*)(x1p + HWs));
    const float* x1n = x1p + 2 * (size_t)HWs;   // overruns into x2 region (unused), safe

    ISSUE_CHUNK(0, 0);
    ISSUE_CHUNK(1, 1);

    int buf = 0;
    for (int ch = 0; ch < NCH; ch++) {
        if (ch + 1 < NCH) asm volatile("cp.async.wait_group 1;\n");
        else              asm volatile("cp.async.wait_group 0;\n");
        __syncthreads();                 // chunk ch visible everywhere; buf reuse safe
        if (ch + 2 < NCH) {
            int nb = buf + 2; if (nb >= NBUF) nb -= NBUF;
            ISSUE_CHUNK(nb, ch + 2);
        }

        const float* xr = &x2s[buf][0];
        #pragma unroll
        for (int cl = 0; cl < CK; cl++) {
            float4 a = xp0; xp0 = xp1;
            xp1 = __ldg((const float4*)x1n); x1n += HWs;

            float v[28];
            const float4* r2 = (const float4*)(xr + (cl * ROWSK + rr) * X2W + w0);
            #pragma unroll
            for (int m = 0; m < 7; m++) ((float4*)v)[m] = r2[m];
            #pragma unroll
            for (int i = 0; i < DD; i++) {
                acc[i].x = fmaf(a.x, v[24 - i], acc[i].x);
                acc[i].y = fmaf(a.y, v[25 - i], acc[i].y);
                acc[i].z = fmaf(a.z, v[26 - i], acc[i].z);
                acc[i].w = fmaf(a.w, v[27 - i], acc[i].w);
            }
        }
        if (++buf >= NBUF) buf = 0;
    }

    size_t obase = (size_t)b * DD * HWs + (size_t)(h0 + rr) * WW + w0;
    #pragma unroll
    for (int i = 0; i < DD; i++)
        *((float4*)(g_corr + obase + (size_t)i * HWs)) = acc[i];
#undef ISSUE_CHUNK
}

// ---------------- kernel 2: whole-plane 3x3 box sum, single sync ----------------
// smem plane: 66 rows (h=-1..64) x stride 200; data cols 4..195, zero halo cols 3,196.
#define BSTR 200
#define TPB2 192

__global__ __launch_bounds__(TPB2)
void box_kernel(float* __restrict__ out) {
    __shared__ float s[66 * BSTR];    // 52.8 KB

    const int t     = threadIdx.x;    // = w column
    const int plane = blockIdx.x;     // b*25 + d

    const float* cp = g_corr + (size_t)plane * HWs;
    float*       op = out    + (size_t)plane * HWs;

    // zero halo rows 0 and 65 (cols 3..196) and halo cols 3,196 of rows 1..64
    for (int i = t; i < 2 * 194; i += TPB2) {
        int r = (i < 194) ? 0 : 65;
        int c = (i < 194 ? i : i - 194) + 3;
        s[r * BSTR + c] = 0.f;
    }
    for (int r = t; r < 64; r += TPB2) { /* t<64 only */ }
    if (t < 64) {
        s[(t + 1) * BSTR + 3]   = 0.f;
        s[(t + 1) * BSTR + 196] = 0.f;
    }

    // load 64x192 plane as float4 (16 per thread), rows 1..64, col offset 4
    #pragma unroll
    for (int k = 0; k < 16; k++) {
        int idx = t + k * TPB2;          // 0..3071
        int row = idx / 48;
        int c4  = idx - row * 48;
        float4 v = __ldg((const float4*)(cp + row * WW + c4 * 4));
        *((float4*)&s[(row + 1) * BSTR + 4 + c4 * 4]) = v;
    }
    __syncthreads();

    // per-column rolling vertical sum of horizontal 3-sums
    const float* col = &s[4 + t];     // col[ (h+1)*BSTR ] = corr(h, t)
    float hsA = 0.f;                                           // hs(-1) = 0
    float hsB = col[BSTR - 1] + col[BSTR] + col[BSTR + 1];     // hs(0)
    #pragma unroll 4
    for (int h = 0; h < HH; h++) {
        const float* p = &col[(h + 2) * BSTR];
        float hsC = p[-1] + p[0] + p[1];                       // hs(h+1)
        op[h * WW + t] = hsA + hsB + hsC;
        hsA = hsB; hsB = hsC;
    }
}

extern "C" void kernel_launch(void* const* d_in, const int* in_sizes, int n_in,
                              void* d_out, int out_size) {
    const float* in = (const float*)d_in[0];
    float* out = (float*)d_out;

    dim3 g1(HH / ROWSK, BB);          // 256 blocks
    corr_kernel<<<g1, TPB1>>>(in);

    box_kernel<<<BB * DD, TPB2>>>(out);  // 400 blocks, one plane each
}

// round 6
// speedup vs baseline: 1.0565x; 1.0095x over previous
#include <cuda_runtime.h>

// Problem constants
#define BB   16
#define CC   256
#define HH   64
#define WW   192
#define DD   25
#define HWs  (HH*WW)
#define CHW  (512*HH*WW)
#define X2OFF ((size_t)CC*HWs)

// corr tiling
#define CK    4
#define ROWSK 4
#define TPB1  192
#define NROWS (CK*ROWSK)
#define X2W   (WW+24)
#define NCH   (CC/CK)        // 64 chunks
#define NBUF  3              // cp.async pipeline depth

__device__ float g_corr[(size_t)BB*DD*HH*WW];

__device__ __forceinline__ void cp_async16(float* dst, const float* src) {
    unsigned d = (unsigned)__cvta_generic_to_shared(dst);
    asm volatile("cp.async.cg.shared.global [%0], [%1], 16;\n" :: "r"(d), "l"(src));
}

__global__ __launch_bounds__(TPB1, 2)
void corr_kernel(const float* __restrict__ in) {
    __shared__ float x2s[NBUF][NROWS * X2W];   // 3 * 13.5 KB

    const int t  = threadIdx.x;
    const int b  = blockIdx.y;
    const int h0 = blockIdx.x * ROWSK;
    const int rr = t / 48;
    const int j  = t - rr * 48;
    const int w0 = 4 * j;

    // zero the 24-col left pads of all buffers (never overwritten)
    for (int idx = t; idx < NBUF * NROWS * 24; idx += TPB1) {
        int bu  = idx / (NROWS * 24);
        int rem = idx - bu * NROWS * 24;
        int row = rem / 24;
        int col = rem - row * 24;
        x2s[bu][row * X2W + col] = 0.0f;
    }

    const float* base   = in + (size_t)b * CHW + (size_t)h0 * WW;
    const float* x2base = base + X2OFF;

#define ISSUE_CHUNK(buf, ch) do {                                              \
    const float* p2 = x2base + (size_t)(ch) * CK * HWs;                        \
    _Pragma("unroll")                                                          \
    for (int it = 0; it < 4; it++) {                                           \
        int q   = it * TPB1 + t;                                               \
        int row = q / 48;                                                      \
        int col = (q - row * 48) * 4;                                          \
        int cl  = row >> 2;                                                    \
        int r   = row & 3;                                                     \
        cp_async16(&x2s[buf][row * X2W + 24 + col],                            \
                   p2 + (size_t)cl * HWs + (size_t)r * WW + col);              \
    }                                                                          \
    asm volatile("cp.async.commit_group;\n");                                  \
} while (0)

    float4 acc[DD];
    #pragma unroll
    for (int i = 0; i < DD; i++) acc[i] = make_float4(0.f, 0.f, 0.f, 0.f);

    // x1 is exclusive per thread: direct coalesced LDG with depth-2 prefetch ring
    const float* x1p = in + (size_t)b * CHW + (size_t)(h0 + rr) * WW + w0;
    float4 xp0 = __ldg((const float4*)x1p);
    float4 xp1 = __ldg((const float4*)(x1p + HWs));
    const float* x1n = x1p + 2 * (size_t)HWs;   // overruns into x2 region (unused), safe

    ISSUE_CHUNK(0, 0);
    ISSUE_CHUNK(1, 1);

    int buf = 0;
    for (int ch = 0; ch < NCH; ch++) {
        if (ch + 1 < NCH) asm volatile("cp.async.wait_group 1;\n");
        else              asm volatile("cp.async.wait_group 0;\n");
        __syncthreads();                 // chunk ch visible everywhere; buf reuse safe
        if (ch + 2 < NCH) {
            int nb = buf + 2; if (nb >= NBUF) nb -= NBUF;
            ISSUE_CHUNK(nb, ch + 2);
        }

        const float* xr = &x2s[buf][0];
        #pragma unroll
        for (int cl = 0; cl < CK; cl++) {
            float4 a = xp0; xp0 = xp1;
            xp1 = __ldg((const float4*)x1n); x1n += HWs;

            float v[28];
            const float4* r2 = (const float4*)(xr + (cl * ROWSK + rr) * X2W + w0);
            #pragma unroll
            for (int m = 0; m < 7; m++) ((float4*)v)[m] = r2[m];
            #pragma unroll
            for (int i = 0; i < DD; i++) {
                acc[i].x = fmaf(a.x, v[24 - i], acc[i].x);
                acc[i].y = fmaf(a.y, v[25 - i], acc[i].y);
                acc[i].z = fmaf(a.z, v[26 - i], acc[i].z);
                acc[i].w = fmaf(a.w, v[27 - i], acc[i].w);
            }
        }
        if (++buf >= NBUF) buf = 0;
    }

    size_t obase = (size_t)b * DD * HWs + (size_t)(h0 + rr) * WW + w0;
    #pragma unroll
    for (int i = 0; i < DD; i++)
        *((float4*)(g_corr + obase + (size_t)i * HWs)) = acc[i];
#undef ISSUE_CHUNK
}

// ---------------- kernel 2: whole-plane 3x3 box sum, single sync ----------------
// smem plane: 66 rows (h=-1..64) x stride 200; data cols 4..195, zero halo cols 3,196.
#define BSTR 200
#define TPB2 192

__global__ __launch_bounds__(TPB2)
void box_kernel(float* __restrict__ out) {
    __shared__ float s[66 * BSTR];    // 52.8 KB

    const int t     = threadIdx.x;    // = w column
    const int plane = blockIdx.x;     // b*25 + d

    const float* cp = g_corr + (size_t)plane * HWs;
    float*       op = out    + (size_t)plane * HWs;

    // zero halo rows 0 and 65 (cols 3..196) and halo cols 3,196 of rows 1..64
    for (int i = t; i < 2 * 194; i += TPB2) {
        int r = (i < 194) ? 0 : 65;
        int c = (i < 194 ? i : i - 194) + 3;
        s[r * BSTR + c] = 0.f;
    }
    for (int r = t; r < 64; r += TPB2) { /* t<64 only */ }
    if (t < 64) {
        s[(t + 1) * BSTR + 3]   = 0.f;
        s[(t + 1) * BSTR + 196] = 0.f;
    }

    // load 64x192 plane as float4 (16 per thread), rows 1..64, col offset 4
    #pragma unroll
    for (int k = 0; k < 16; k++) {
        int idx = t + k * TPB2;          // 0..3071
        int row = idx / 48;
        int c4  = idx - row * 48;
        float4 v = __ldg((const float4*)(cp + row * WW + c4 * 4));
        *((float4*)&s[(row + 1) * BSTR + 4 + c4 * 4]) = v;
    }
    __syncthreads();

    // per-column rolling vertical sum of horizontal 3-sums
    const float* col = &s[4 + t];     // col[ (h+1)*BSTR ] = corr(h, t)
    float hsA = 0.f;                                           // hs(-1) = 0
    float hsB = col[BSTR - 1] + col[BSTR] + col[BSTR + 1];     // hs(0)
    #pragma unroll 4
    for (int h = 0; h < HH; h++) {
        const float* p = &col[(h + 2) * BSTR];
        float hsC = p[-1] + p[0] + p[1];                       // hs(h+1)
        op[h * WW + t] = hsA + hsB + hsC;
        hsA = hsB; hsB = hsC;
    }
}

extern "C" void kernel_launch(void* const* d_in, const int* in_sizes, int n_in,
                              void* d_out, int out_size) {
    const float* in = (const float*)d_in[0];
    float* out = (float*)d_out;

    dim3 g1(HH / ROWSK, BB);          // 256 blocks
    corr_kernel<<<g1, TPB1>>>(in);

    box_kernel<<<BB * DD, TPB2>>>(out);  // 400 blocks, one plane each
}